// round 3
// baseline (speedup 1.0000x reference)
#include <cuda_runtime.h>
#include <math_constants.h>

#define BB 32
#define LL 2048
#define DD 1024

#define NT     256              // threads per block
#define NBLK   256              // total blocks (all co-resident: barrier-safe)
#define GROUPS 8                // concurrent batches per wave (8*8MB=64MB < L2)
#define GSZ    (NBLK / GROUPS)  // 32 blocks cooperating on one batch
#define WAVES  (BB / GROUPS)    // 4
#define RPB    (LL / GSZ)       // 64 rows per block
#define KPT    (LL / NT)        // 8 f-values per thread in softmax

// Scratch + barrier state: __device__ globals (no allocation allowed).
__device__ float g_f1[BB * LL];
__device__ float g_f2[BB * LL];
__device__ int   g_cnt[BB];     // monotonic ticket counters (replay-safe)

__global__ __launch_bounds__(NT) void k_fused(const float* __restrict__ emb,
                                              const float* __restrict__ w1,
                                              const float* __restrict__ w2,
                                              const float* __restrict__ bias,
                                              float* __restrict__ out) {
    __shared__ float4 sw1[DD / 4];
    __shared__ float4 sw2[DD / 4];
    __shared__ float  sred[NT];
    __shared__ int    sidx[NT];
    __shared__ float  swt[RPB];

    const int t = threadIdx.x;
    // Stage projection weights once (constant across waves).
    sw1[t] = ((const float4*)w1)[t];
    sw2[t] = ((const float4*)w2)[t];
    const float bv = bias[0];

    const int group = blockIdx.x / GSZ;   // which concurrent batch slot (0..7)
    const int g     = blockIdx.x % GSZ;   // rank within the batch group (0..31)
    const int warp  = t >> 5;
    const int lane  = t & 31;
    __syncthreads();

    for (int wave = 0; wave < WAVES; wave++) {
        const int b    = wave * GROUPS + group;
        const int row0 = g * RPB;
        const int fb   = b * LL;
        const float* ebase = emb + ((size_t)b * LL + row0) * DD;

        // ---------------- Phase 1: f1/f2 for own 64 rows (HBM read #1) ----
        for (int r = warp; r < RPB; r += NT / 32) {
            const float4* e = (const float4*)(ebase + (size_t)r * DD);
            float a1 = 0.f, a2 = 0.f;
#pragma unroll
            for (int k = 0; k < 8; k++) {
                int idx = k * 32 + lane;
                float4 ev = e[idx];
                float4 u1 = sw1[idx], u2 = sw2[idx];
                a1 += ev.x * u1.x + ev.y * u1.y + ev.z * u1.z + ev.w * u1.w;
                a2 += ev.x * u2.x + ev.y * u2.y + ev.z * u2.z + ev.w * u2.w;
            }
#pragma unroll
            for (int o = 16; o; o >>= 1) {
                a1 += __shfl_xor_sync(0xffffffffu, a1, o);
                a2 += __shfl_xor_sync(0xffffffffu, a2, o);
            }
            if (lane == 0) {
                g_f1[fb + row0 + r] = a1;
                g_f2[fb + row0 + r] = a2;
            }
        }
        __syncthreads();

        // ---------------- Per-batch barrier (32 blocks) --------------------
        // Monotonic tickets: no reset needed, safe across graph replays.
        if (t == 0) {
            __threadfence();                          // release f1/f2 writes
            int ticket = atomicAdd(&g_cnt[b], 1) + 1;
            int target = ((ticket + GSZ - 1) / GSZ) * GSZ;
            while (*(volatile int*)&g_cnt[b] < target) __nanosleep(64);
            __threadfence();                          // acquire
        }
        __syncthreads();

        // ---------------- Softmax stats (redundant per block, 16KB in L2) --
        float f1v[KPT], f2v[KPT];
#pragma unroll
        for (int k = 0; k < KPT; k++) {
            int l = k * NT + t;
            f1v[k] = __ldcg(&g_f1[fb + l]);   // bypass L1: cross-block data
            f2v[k] = __ldcg(&g_f2[fb + l]);
        }
        // argmax of f2 (tie-break: lowest index, matching jax.lax.top_k)
        float mv = -CUDART_INF_F;
        int   mi = LL;
#pragma unroll
        for (int k = 0; k < KPT; k++) {
            int l = k * NT + t;                       // increasing l: '>' keeps lowest
            if (f2v[k] > mv) { mv = f2v[k]; mi = l; }
        }
        sred[t] = mv; sidx[t] = mi;
        __syncthreads();
        for (int s = NT / 2; s; s >>= 1) {
            if (t < s) {
                if (sred[t + s] > sred[t] ||
                    (sred[t + s] == sred[t] && sidx[t + s] < sidx[t])) {
                    sred[t] = sred[t + s];
                    sidx[t] = sidx[t + s];
                }
            }
            __syncthreads();
        }
        const float v0 = sred[0];
        const int   i0 = sidx[0];
        __syncthreads();

        // second max over l != i0
        float m2 = -CUDART_INF_F;
#pragma unroll
        for (int k = 0; k < KPT; k++) {
            int l = k * NT + t;
            if (l != i0) m2 = fmaxf(m2, f2v[k]);
        }
        sred[t] = m2;
        __syncthreads();
        for (int s = NT / 2; s; s >>= 1) {
            if (t < s) sred[t] = fmaxf(sred[t], sred[t + s]);
            __syncthreads();
        }
        const float v1 = sred[0];
        __syncthreads();

        // max of g = f1 + offdiag + bias
        float gmax = -CUDART_INF_F;
#pragma unroll
        for (int k = 0; k < KPT; k++) {
            int l = k * NT + t;
            gmax = fmaxf(gmax, f1v[k] + ((l == i0) ? v1 : v0) + bv);
        }
        sred[t] = gmax;
        __syncthreads();
        for (int s = NT / 2; s; s >>= 1) {
            if (t < s) sred[t] = fmaxf(sred[t], sred[t + s]);
            __syncthreads();
        }
        gmax = sred[0];
        __syncthreads();

        // sum of exp
        float ssum = 0.f;
#pragma unroll
        for (int k = 0; k < KPT; k++) {
            int l = k * NT + t;
            ssum += expf(f1v[k] + ((l == i0) ? v1 : v0) + bv - gmax);
        }
        sred[t] = ssum;
        __syncthreads();
        for (int s = NT / 2; s; s >>= 1) {
            if (t < s) sred[t] += sred[t + s];
            __syncthreads();
        }
        const float invZ = 1.f / sred[0];
        __syncthreads();

        // weights for own 64 rows into smem
        if (t < RPB) {
            int row = row0 + t;
            float f1r = __ldcg(&g_f1[fb + row]);
            swt[t] = expf(f1r + ((row == i0) ? v1 : v0) + bv - gmax) * invZ;
        }
        __syncthreads();

        // ---------------- Phase 3: weighted sum over own rows (L2 re-read) -
        // Thread t owns float4 column t across all 64 rows.
        const float4* e = (const float4*)ebase + t;
        float4 acc = make_float4(0.f, 0.f, 0.f, 0.f);
#pragma unroll 4
        for (int r = 0; r < RPB; r++) {
            float  w  = swt[r];
            float4 ev = e[(size_t)r * (DD / 4)];
            acc.x += w * ev.x;
            acc.y += w * ev.y;
            acc.z += w * ev.z;
            acc.w += w * ev.w;
        }
        float* o = out + b * DD + t * 4;
        atomicAdd(o + 0, acc.x);
        atomicAdd(o + 1, acc.y);
        atomicAdd(o + 2, acc.z);
        atomicAdd(o + 3, acc.w);

        __syncthreads();   // protect smem reuse before next wave
    }
}

extern "C" void kernel_launch(void* const* d_in, const int* in_sizes, int n_in,
                              void* d_out, int out_size) {
    const float* emb  = (const float*)d_in[0];
    const float* w1   = (const float*)d_in[1];
    const float* w2   = (const float*)d_in[2];
    const float* bias = (const float*)d_in[3];
    float* out = (float*)d_out;

    cudaMemsetAsync(out, 0, (size_t)BB * DD * sizeof(float));
    k_fused<<<NBLK, NT>>>(emb, w1, w2, bias, out);
}

// round 4
// speedup vs baseline: 2.1043x; 2.1043x over previous
#include <cuda_runtime.h>
#include <math_constants.h>

#define BB 32
#define LL 2048
#define DD 1024

#define NT        256                 // threads per block
#define RPB       32                  // rows per K1 block
#define BLKS_PB   (LL / RPB)          // 64 partial blocks per batch
#define NBLK1     (BB * BLKS_PB)      // 2048
#define CHUNK     8                   // rows processed per smem round (== warps)

// Scratch (__device__ globals: no allocation allowed in kernel_launch).
__device__ float4 g_acc[NBLK1 * (DD / 4)];   // 8 MB partial vectors
__device__ float  g_m  [NBLK1];
__device__ float  g_z  [NBLK1];
__device__ float  g_v0 [NBLK1];              // local max of f2
__device__ int    g_i0 [NBLK1];
__device__ float  g_f10[NBLK1];              // f1 at local argmax
__device__ float  g_v1 [NBLK1];              // local 2nd max of f2
__device__ int    g_i1 [NBLK1];
__device__ float  g_f11[NBLK1];

// ---------------------------------------------------------------------------
// K1: one pass over the embedding. Each block: 32 rows of one batch.
// Thread t owns float4 column t. Per 8-row chunk: load rows, transpose-reduce
// dot products through smem (warp j reduces row j), then flash-accumulate.
// ---------------------------------------------------------------------------
__global__ __launch_bounds__(NT) void k_pass1(const float* __restrict__ emb,
                                              const float* __restrict__ w1,
                                              const float* __restrict__ w2) {
    __shared__ float s1[CHUNK][NT];
    __shared__ float s2[CHUNK][NT];
    __shared__ float sf1[CHUNK];
    __shared__ float sf2[CHUNK];

    const int t    = threadIdx.x;
    const int warp = t >> 5;
    const int lane = t & 31;
    const int b    = blockIdx.x / BLKS_PB;
    const int blk  = blockIdx.x % BLKS_PB;
    const int row0 = blk * RPB;

    const float4* e   = (const float4*)(emb + ((size_t)b * LL + row0) * DD) + t;
    const float4  w1c = ((const float4*)w1)[t];
    const float4  w2c = ((const float4*)w2)[t];

    float4 acc = make_float4(0.f, 0.f, 0.f, 0.f);
    float  m = -CUDART_INF_F, Z = 0.f;
    float  v0 = -CUDART_INF_F, v1 = -CUDART_INF_F;
    float  f10 = 0.f, f11 = 0.f;
    int    i0 = 0x7fffffff, i1 = 0x7fffffff;

    for (int c0 = 0; c0 < RPB; c0 += CHUNK) {
        float4 ev[CHUNK];
#pragma unroll
        for (int j = 0; j < CHUNK; j++)               // 8 independent LDG.128
            ev[j] = e[(size_t)(c0 + j) * (DD / 4)];
#pragma unroll
        for (int j = 0; j < CHUNK; j++) {
            s1[j][t] = ev[j].x * w1c.x + ev[j].y * w1c.y + ev[j].z * w1c.z + ev[j].w * w1c.w;
            s2[j][t] = ev[j].x * w2c.x + ev[j].y * w2c.y + ev[j].z * w2c.z + ev[j].w * w2c.w;
        }
        __syncthreads();
        {   // warp j reduces row j's 256 partials
            float a = 0.f, c = 0.f;
#pragma unroll
            for (int i = 0; i < NT / 32; i++) {
                a += s1[warp][lane + 32 * i];
                c += s2[warp][lane + 32 * i];
            }
#pragma unroll
            for (int o = 16; o; o >>= 1) {
                a += __shfl_xor_sync(0xffffffffu, a, o);
                c += __shfl_xor_sync(0xffffffffu, c, o);
            }
            if (lane == 0) { sf1[warp] = a; sf2[warp] = c; }
        }
        __syncthreads();

        float f1v[CHUNK], f2v[CHUNK];
        float cmax = -CUDART_INF_F;
#pragma unroll
        for (int j = 0; j < CHUNK; j++) {
            f1v[j] = sf1[j];
            f2v[j] = sf2[j];
            cmax = fmaxf(cmax, f1v[j]);
        }
        const float mnew  = fmaxf(m, cmax);
        const float scale = __expf(m - mnew);        // 0 on first chunk (m=-inf)
        acc.x *= scale; acc.y *= scale; acc.z *= scale; acc.w *= scale;
        Z *= scale;
#pragma unroll
        for (int j = 0; j < CHUNK; j++) {
            const float w = __expf(f1v[j] - mnew);
            Z += w;
            acc.x += w * ev[j].x;
            acc.y += w * ev[j].y;
            acc.z += w * ev[j].z;
            acc.w += w * ev[j].w;
            // local top-2 of f2 (rows visited in ascending index: '>' keeps lowest)
            const int l = row0 + c0 + j;
            if (f2v[j] > v0) {
                v1 = v0; i1 = i0; f11 = f10;
                v0 = f2v[j]; i0 = l; f10 = f1v[j];
            } else if (f2v[j] > v1) {
                v1 = f2v[j]; i1 = l; f11 = f1v[j];
            }
        }
        m = mnew;
        __syncthreads();                              // smem reuse next chunk
    }

    g_acc[blockIdx.x * (DD / 4) + t] = acc;
    if (t == 0) {
        g_m  [blockIdx.x] = m;
        g_z  [blockIdx.x] = Z;
        g_v0 [blockIdx.x] = v0;  g_i0[blockIdx.x] = i0;  g_f10[blockIdx.x] = f10;
        g_v1 [blockIdx.x] = v1;  g_i1[blockIdx.x] = i1;  g_f11[blockIdx.x] = f11;
    }
}

// ---------------------------------------------------------------------------
// K2: per batch (32 blocks), combine 64 partials. Stats reduced redundantly
// per thread (64 tiny loads); vector combine: thread t owns float4 column t.
// ---------------------------------------------------------------------------
__global__ __launch_bounds__(NT) void k_pass2(const float* __restrict__ emb,
                                              float* __restrict__ out) {
    const int b    = blockIdx.x;
    const int t    = threadIdx.x;
    const int base = b * BLKS_PB;

    // global max of local m's
    float m_g = -CUDART_INF_F;
#pragma unroll 8
    for (int k = 0; k < BLKS_PB; k++) m_g = fmaxf(m_g, g_m[base + k]);

    // global Z and global top-2 of f2 (union of per-block top-2 candidates)
    float Z = 0.f;
    float v0 = -CUDART_INF_F, v1 = -CUDART_INF_F, f10 = 0.f;
    int   i0 = 0x7fffffff;
    for (int k = 0; k < BLKS_PB; k++) {
        Z += g_z[base + k] * __expf(g_m[base + k] - m_g);
        float cv0 = g_v0[base + k], cf0 = g_f10[base + k];
        int   ci0 = g_i0[base + k];
        float cv1 = g_v1[base + k];
        if (cv0 > v0 || (cv0 == v0 && ci0 < i0)) {
            v1 = v0;
            v0 = cv0; i0 = ci0; f10 = cf0;
        } else if (cv0 > v1) {
            v1 = cv0;
        }
        if (cv1 > v1) v1 = cv1;   // second candidate can only update v1
    }

    // correction at the global argmax position: weight factor exp(v1-v0) there
    const float c    = (__expf(v1 - v0) - 1.f) * __expf(f10 - m_g);
    const float invZ = 1.f / (Z + c);

    // combine partial vectors
    float4 acc = make_float4(0.f, 0.f, 0.f, 0.f);
    for (int k = 0; k < BLKS_PB; k++) {
        const float  coef = __expf(g_m[base + k] - m_g);
        const float4 p    = g_acc[(base + k) * (DD / 4) + t];
        acc.x += coef * p.x;
        acc.y += coef * p.y;
        acc.z += coef * p.z;
        acc.w += coef * p.w;
    }
    // add correction row (4 KB read, L2/HBM — one row per batch)
    const float4 er = ((const float4*)(emb + ((size_t)b * LL + i0) * DD))[t];
    acc.x = (acc.x + c * er.x) * invZ;
    acc.y = (acc.y + c * er.y) * invZ;
    acc.z = (acc.z + c * er.z) * invZ;
    acc.w = (acc.w + c * er.w) * invZ;

    ((float4*)out)[b * (DD / 4) + t] = acc;
}

// ---------------------------------------------------------------------------
// Launch: K1 (single embedding pass) -> K2 (combine). Graph-capturable,
// deterministic (no atomics), out fully written by K2 (no memset needed).
// ---------------------------------------------------------------------------
extern "C" void kernel_launch(void* const* d_in, const int* in_sizes, int n_in,
                              void* d_out, int out_size) {
    const float* emb = (const float*)d_in[0];
    const float* w1  = (const float*)d_in[1];
    const float* w2  = (const float*)d_in[2];
    // d_in[3] (bias) is mathematically irrelevant: constant shift cancels in softmax.
    float* out = (float*)d_out;

    k_pass1<<<NBLK1, NT>>>(emb, w1, w2);
    k_pass2<<<BB, NT>>>(emb, out);
}